// round 14
// baseline (speedup 1.0000x reference)
#include <cuda_runtime.h>

// out = noised + 0.1f * noise, elementwise over 50,331,648 fp32.
// HBM-bound: 604 MB traffic. R6: 90.2us harness / 80.0us kernel, DRAM 87.6%.
// R7: 4x float4 per thread (MLP_p1=8 front-batched LDG.128), grid 12288.

__global__ void __launch_bounds__(256, 8)
gaussian_noise_axpy(const float4* __restrict__ noised,
                    const float4* __restrict__ noise,
                    float4* __restrict__ out,
                    int n4)
{
    int base = blockIdx.x * (blockDim.x * 4) + threadIdx.x;
    int i0 = base;
    int i1 = base + blockDim.x;
    int i2 = base + 2 * blockDim.x;
    int i3 = base + 3 * blockDim.x;

    if (i3 < n4) {
        // Front-batch all 8 loads for maximum MLP.
        float4 a0 = __ldcs(&noised[i0]);
        float4 a1 = __ldcs(&noised[i1]);
        float4 a2 = __ldcs(&noised[i2]);
        float4 a3 = __ldcs(&noised[i3]);
        float4 b0 = __ldcs(&noise[i0]);
        float4 b1 = __ldcs(&noise[i1]);
        float4 b2 = __ldcs(&noise[i2]);
        float4 b3 = __ldcs(&noise[i3]);
        float4 r0, r1, r2, r3;
        r0.x = fmaf(0.1f, b0.x, a0.x); r0.y = fmaf(0.1f, b0.y, a0.y);
        r0.z = fmaf(0.1f, b0.z, a0.z); r0.w = fmaf(0.1f, b0.w, a0.w);
        r1.x = fmaf(0.1f, b1.x, a1.x); r1.y = fmaf(0.1f, b1.y, a1.y);
        r1.z = fmaf(0.1f, b1.z, a1.z); r1.w = fmaf(0.1f, b1.w, a1.w);
        r2.x = fmaf(0.1f, b2.x, a2.x); r2.y = fmaf(0.1f, b2.y, a2.y);
        r2.z = fmaf(0.1f, b2.z, a2.z); r2.w = fmaf(0.1f, b2.w, a2.w);
        r3.x = fmaf(0.1f, b3.x, a3.x); r3.y = fmaf(0.1f, b3.y, a3.y);
        r3.z = fmaf(0.1f, b3.z, a3.z); r3.w = fmaf(0.1f, b3.w, a3.w);
        __stcs(&out[i0], r0);
        __stcs(&out[i1], r1);
        __stcs(&out[i2], r2);
        __stcs(&out[i3], r3);
    } else {
        // Remainder path (not taken for the benchmarked shape).
        #pragma unroll
        for (int k = 0; k < 4; k++) {
            int i = base + k * blockDim.x;
            if (i < n4) {
                float4 a = __ldcs(&noised[i]);
                float4 b = __ldcs(&noise[i]);
                float4 r;
                r.x = fmaf(0.1f, b.x, a.x);
                r.y = fmaf(0.1f, b.y, a.y);
                r.z = fmaf(0.1f, b.z, a.z);
                r.w = fmaf(0.1f, b.w, a.w);
                __stcs(&out[i], r);
            }
        }
    }
}

// Tail handler for n not divisible by 4 (defensive; current shape is divisible).
__global__ void gaussian_noise_tail(const float* __restrict__ noised,
                                    const float* __restrict__ noise,
                                    float* __restrict__ out,
                                    int start, int n)
{
    int i = start + blockIdx.x * blockDim.x + threadIdx.x;
    if (i < n) {
        out[i] = fmaf(0.1f, noise[i], noised[i]);
    }
}

extern "C" void kernel_launch(void* const* d_in, const int* in_sizes, int n_in,
                              void* d_out, int out_size)
{
    const float* noised = (const float*)d_in[0];
    const float* noise  = (const float*)d_in[1];
    float* out = (float*)d_out;
    int n = in_sizes[0];

    int n4 = n / 4;
    if (n4 > 0) {
        int threads = 256;
        int per_block = threads * 4;
        int blocks = (n4 + per_block - 1) / per_block;
        gaussian_noise_axpy<<<blocks, threads>>>(
            (const float4*)noised, (const float4*)noise, (float4*)out, n4);
    }
    int rem = n - n4 * 4;
    if (rem > 0) {
        gaussian_noise_tail<<<1, 256>>>(noised, noise, out, n4 * 4, n);
    }
}

// round 16
// speedup vs baseline: 1.0028x; 1.0028x over previous
#include <cuda_runtime.h>

// out = noised + 0.1f * noise, elementwise over 50,331,648 fp32.
// HBM-bound: 604 MB traffic. Final: R6 config (2x float4/thread + .cs hints).
// Sweep: 1x=80.6us, 2x=80.0us (DRAM 87.6%), 4x=81.0us -> 2x is the optimum.

__global__ void __launch_bounds__(256, 8)
gaussian_noise_axpy(const float4* __restrict__ noised,
                    const float4* __restrict__ noise,
                    float4* __restrict__ out,
                    int n4)
{
    // 2 float4 per thread, front-batched loads for MLP.
    int i0 = blockIdx.x * (blockDim.x * 2) + threadIdx.x;
    int i1 = i0 + blockDim.x;

    if (i1 < n4) {
        float4 a0 = __ldcs(&noised[i0]);
        float4 a1 = __ldcs(&noised[i1]);
        float4 b0 = __ldcs(&noise[i0]);
        float4 b1 = __ldcs(&noise[i1]);
        float4 r0, r1;
        r0.x = fmaf(0.1f, b0.x, a0.x);
        r0.y = fmaf(0.1f, b0.y, a0.y);
        r0.z = fmaf(0.1f, b0.z, a0.z);
        r0.w = fmaf(0.1f, b0.w, a0.w);
        r1.x = fmaf(0.1f, b1.x, a1.x);
        r1.y = fmaf(0.1f, b1.y, a1.y);
        r1.z = fmaf(0.1f, b1.z, a1.z);
        r1.w = fmaf(0.1f, b1.w, a1.w);
        __stcs(&out[i0], r0);
        __stcs(&out[i1], r1);
    } else if (i0 < n4) {
        float4 a0 = __ldcs(&noised[i0]);
        float4 b0 = __ldcs(&noise[i0]);
        float4 r0;
        r0.x = fmaf(0.1f, b0.x, a0.x);
        r0.y = fmaf(0.1f, b0.y, a0.y);
        r0.z = fmaf(0.1f, b0.z, a0.z);
        r0.w = fmaf(0.1f, b0.w, a0.w);
        __stcs(&out[i0], r0);
    }
}

// Tail handler for n not divisible by 4 (defensive; current shape is divisible).
__global__ void gaussian_noise_tail(const float* __restrict__ noised,
                                    const float* __restrict__ noise,
                                    float* __restrict__ out,
                                    int start, int n)
{
    int i = start + blockIdx.x * blockDim.x + threadIdx.x;
    if (i < n) {
        out[i] = fmaf(0.1f, noise[i], noised[i]);
    }
}

extern "C" void kernel_launch(void* const* d_in, const int* in_sizes, int n_in,
                              void* d_out, int out_size)
{
    const float* noised = (const float*)d_in[0];
    const float* noise  = (const float*)d_in[1];
    float* out = (float*)d_out;
    int n = in_sizes[0];

    int n4 = n / 4;
    if (n4 > 0) {
        int threads = 256;
        int per_block = threads * 2;
        int blocks = (n4 + per_block - 1) / per_block;
        gaussian_noise_axpy<<<blocks, threads>>>(
            (const float4*)noised, (const float4*)noise, (float4*)out, n4);
    }
    int rem = n - n4 * 4;
    if (rem > 0) {
        gaussian_noise_tail<<<1, 256>>>(noised, noise, out, n4 * 4, n);
    }
}